// round 17
// baseline (speedup 1.0000x reference)
#include <cuda_runtime.h>

// out[b,h,w,c] = sum_j w[j,c] * t_j[b,h,w,c]
// t_j = (8,128,128,128) fp32 contiguous; w = (5,128) fp32.
// N = 16,777,216 floats -> 4,194,304 float4. HBM-bound: 384 MiB mandatory traffic.
//
// FINAL SHAPE (R7/R15 config @ 85% DRAM, 56.1us kernel), with 512-thread blocks
// to halve CTA count (8192 blocks). Exploration summary:
//  - 1 float4/thread, MLP=5 front-batched LDG.128: 56.1-57.2us (ceiling band)
//  - 2x unroll @32 regs: spills -> 82.5us; @60 regs: occ drop -> 59.3us
//  - persistent 1216-block grid-stride: 56.9us (identical -> wave cost ~0)
//  - streaming hints (__ldcs/__stcs): neutral-to-slightly-positive
// All variants pin at ~6650-6770 GB/s = the path-independent LTS/HBM ceiling
// (B300: ~6300 B/cyc, LDG == TMA), i.e. the roofline for 5R+1W fp32 streaming.

__global__ __launch_bounds__(512, 2)
void merge5_kernel(const float4* __restrict__ t1,
                   const float4* __restrict__ t2,
                   const float4* __restrict__ t3,
                   const float4* __restrict__ t4,
                   const float4* __restrict__ t5,
                   const float4* __restrict__ w,   // (5,32) float4 = (5,128) floats
                   float4* __restrict__ out,
                   int n4) {
    int idx = blockIdx.x * blockDim.x + threadIdx.x;
    if (idx >= n4) return;

    int cw = idx & 31;  // float4 index within the 128-channel row

    // Weights: 2.5 KB, cache-resident, warp-broadcast -> default policy.
    float4 w0 = __ldg(&w[0 * 32 + cw]);
    float4 w1 = __ldg(&w[1 * 32 + cw]);
    float4 w2 = __ldg(&w[2 * 32 + cw]);
    float4 w3 = __ldg(&w[3 * 32 + cw]);
    float4 w4 = __ldg(&w[4 * 32 + cw]);

    // 5 independent streaming loads, front-batched (MLP=5/thread).
    float4 a = __ldcs(&t1[idx]);
    float4 b = __ldcs(&t2[idx]);
    float4 c = __ldcs(&t3[idx]);
    float4 d = __ldcs(&t4[idx]);
    float4 e = __ldcs(&t5[idx]);

    float4 o;
    o.x = a.x * w0.x + b.x * w1.x + c.x * w2.x + d.x * w3.x + e.x * w4.x;
    o.y = a.y * w0.y + b.y * w1.y + c.y * w2.y + d.y * w3.y + e.y * w4.y;
    o.z = a.z * w0.z + b.z * w1.z + c.z * w2.z + d.z * w3.z + e.z * w4.z;
    o.w = a.w * w0.w + b.w * w1.w + c.w * w2.w + d.w * w3.w + e.w * w4.w;

    __stcs(&out[idx], o);
}

extern "C" void kernel_launch(void* const* d_in, const int* in_sizes, int n_in,
                              void* d_out, int out_size) {
    const float4* t1 = (const float4*)d_in[0];
    const float4* t2 = (const float4*)d_in[1];
    const float4* t3 = (const float4*)d_in[2];
    const float4* t4 = (const float4*)d_in[3];
    const float4* t5 = (const float4*)d_in[4];
    const float4* w  = (const float4*)d_in[5];
    float4* out = (float4*)d_out;

    int n4 = out_size / 4;  // 4,194,304
    int threads = 512;
    int blocks = (n4 + threads - 1) / threads;  // 8192 blocks
    merge5_kernel<<<blocks, threads>>>(t1, t2, t3, t4, t5, w, out, n4);
}